// round 3
// baseline (speedup 1.0000x reference)
#include <cuda_runtime.h>
#include <math.h>

#define VOCAB 50000
#define EMB   300
#define SEQ   80
#define HID   128
#define BATCH 4096

typedef unsigned long long ull;

// Scratch: projected embedding table P = emb @ Wxh  (25.6 MB, L2-resident at use)
__device__ float g_P[VOCAB * HID];

// ---- packed f32x2 helpers (sm_100 PTX ISA 8.6) ----
__device__ __forceinline__ ull fma2(ull a, ull b, ull c) {
    ull d; asm("fma.rn.f32x2 %0, %1, %2, %3;" : "=l"(d) : "l"(a), "l"(b), "l"(c)); return d;
}
__device__ __forceinline__ ull add2(ull a, ull b) {
    ull d; asm("add.rn.f32x2 %0, %1, %2;" : "=l"(d) : "l"(a), "l"(b)); return d;
}
__device__ __forceinline__ ull pk(float lo, float hi) {
    ull d; asm("mov.b64 %0, {%1, %2};" : "=l"(d) : "f"(lo), "f"(hi)); return d;
}
__device__ __forceinline__ float2 upk(ull v) {
    float2 r; asm("mov.b64 {%0, %1}, %2;" : "=f"(r.x), "=f"(r.y) : "l"(v)); return r;
}

// ---------------------------------------------------------------------------
// Kernel A: P[v][j] = sum_e emb[v][e] * Wxh[e][j]
// 128x128 tile, TK=4, 256 threads, 8x8 per-thread tile, f32x2 packed FMA.
// A rows stored DUPLICATED in smem (8B entries) so fma2's broadcast operand
// comes straight from LDS.128; B cols pack naturally from contiguous floats.
// ---------------------------------------------------------------------------
__global__ __launch_bounds__(256) void proj_kernel(const float* __restrict__ emb,
                                                   const float* __restrict__ Wxh) {
    __shared__ ull   As_d[4][128];   // [k][row] duplicated (v,v)
    __shared__ float Bs[4][128];     // [k][col]

    const int tid = threadIdx.x;
    const int v0  = blockIdx.x * 128;
    const int tr  = tid >> 4;   // 0..15 -> rows tr*8..+7
    const int tc  = tid & 15;   // 0..15 -> cols tc*8..+7

    ull acc[8][4];
#pragma unroll
    for (int i = 0; i < 8; i++)
#pragma unroll
        for (int jp = 0; jp < 4; jp++) acc[i][jp] = 0ull;

    const bool isA = (tid < 128);
    const int  av  = v0 + tid;                 // A: vocab row
    const int  bk  = (tid - 128) >> 5;         // B: k row 0..3
    const int  bj  = ((tid - 128) & 31) * 4;   // B: col group

    float4 ld;
    if (isA) {
        ld = (av < VOCAB) ? *(const float4*)&emb[(long)av * EMB + 0]
                          : make_float4(0.f, 0.f, 0.f, 0.f);
    } else {
        ld = *(const float4*)&Wxh[(0 + bk) * HID + bj];
    }

    for (int e0 = 0; e0 < EMB; e0 += 4) {
        if (isA) {
            As_d[0][tid] = pk(ld.x, ld.x);
            As_d[1][tid] = pk(ld.y, ld.y);
            As_d[2][tid] = pk(ld.z, ld.z);
            As_d[3][tid] = pk(ld.w, ld.w);
        } else {
            *(float4*)&Bs[bk][bj] = ld;
        }
        __syncthreads();

        const int en = e0 + 4;
        if (en < EMB) {
            if (isA) {
                ld = (av < VOCAB) ? *(const float4*)&emb[(long)av * EMB + en]
                                  : make_float4(0.f, 0.f, 0.f, 0.f);
            } else {
                ld = *(const float4*)&Wxh[(en + bk) * HID + bj];
            }
        }

#pragma unroll
        for (int k = 0; k < 4; k++) {
            const ulonglong2* ap = (const ulonglong2*)&As_d[k][tr * 8];
            ulonglong2 a01 = ap[0], a23 = ap[1], a45 = ap[2], a67 = ap[3];
            const ulonglong2* bp = (const ulonglong2*)&Bs[k][tc * 8];
            ulonglong2 b01 = bp[0], b23 = bp[1];
            ull ad[8] = {a01.x, a01.y, a23.x, a23.y, a45.x, a45.y, a67.x, a67.y};
            ull bb[4] = {b01.x, b01.y, b23.x, b23.y};
#pragma unroll
            for (int i = 0; i < 8; i++)
#pragma unroll
                for (int jp = 0; jp < 4; jp++)
                    acc[i][jp] = fma2(ad[i], bb[jp], acc[i][jp]);
        }
        __syncthreads();
    }

#pragma unroll
    for (int i = 0; i < 8; i++) {
        const int v = v0 + tr * 8 + i;
        if (v < VOCAB) {
            ulonglong2 s0; s0.x = acc[i][0]; s0.y = acc[i][1];
            ulonglong2 s1; s1.x = acc[i][2]; s1.y = acc[i][3];
            *(ulonglong2*)&g_P[(long)v * HID + tc * 8]     = s0;
            *(ulonglong2*)&g_P[(long)v * HID + tc * 8 + 4] = s1;
        }
    }
}

// ---------------------------------------------------------------------------
// Kernel B: recurrence. grid=128, 256 threads (8 warps = 4 rowgroups x
// 2 colgroups). Block owns exactly 32 batch rows; warp = 8 rows x 64 cols;
// thread = 8 rows x 2 cols. h stored DUPLICATED ((h,h) 8B entries, stride-34
// padded) so the fma2 broadcast operand is a straight LDS.128.
// Per k: 1 LDS.64 (w pair) + 4 LDS.128 (8 row-dups) + 8 FMA2.
// Double-buffered h: one barrier per timestep.
// ---------------------------------------------------------------------------
#define RNBLK 128
#define NSLOT 32
#define HSTR  34        // padded entries per k-row (write-conflict mitigation)
#define HBUF  (HID * HSTR)

__global__ __launch_bounds__(256) void rnn_kernel(const int* __restrict__ x,
                                                  const float* __restrict__ Whh,
                                                  const float* __restrict__ bh,
                                                  const float* __restrict__ Wd,
                                                  const float* __restrict__ bd,
                                                  float* __restrict__ out) {
    extern __shared__ char sm[];
    float* Whh_sh = (float*)sm;                            // 64 KB
    ull*   hD     = (ull*)(sm + 65536);                    // 2*HBUF entries (68 KB)
    int*   tok_sh = (int*)(sm + 65536 + 2 * HBUF * 8);     // NSLOT*SEQ ints (10 KB)
    float* red    = (float*)(sm + 65536 + 2 * HBUF * 8 + NSLOT * SEQ * 4); // 64 floats

    const int tid   = threadIdx.x;
    const int lane  = tid & 31;
    const int wid   = tid >> 5;
    const int rg    = wid >> 1;          // rowgroup 0..3
    const int cg    = wid & 1;           // colgroup 0..1
    const int j0    = cg * 64 + lane * 2;
    const int slot0 = rg * 8;
    const int b0    = blockIdx.x * NSLOT;

    // Load Whh (vectorized)
    {
        const float4* src = (const float4*)Whh;
        float4* dst = (float4*)Whh_sh;
        for (int i = tid; i < HID * HID / 4; i += 256) dst[i] = src[i];
    }
    // Tokens: contiguous copy (rows b0..b0+31)
    for (int i = tid; i < NSLOT * SEQ; i += 256) tok_sh[i] = x[b0 * SEQ + i];
    // Zero h buffer 0
    for (int i = tid; i < HBUF; i += 256) hD[i] = 0ull;

    const ull bh2 = pk(bh[j0], bh[j0 + 1]);
    __syncthreads();

    // Prefetch step-0 inputs
    ull xv[8];
#pragma unroll
    for (int r = 0; r < 8; r++) {
        const int tok = tok_sh[(slot0 + r) * SEQ + 0];
        float2 p = *(const float2*)&g_P[(long)tok * HID + j0];
        xv[r] = add2(pk(p.x, p.y), bh2);
    }

    float vlast[8][2];

    for (int t = 0; t < SEQ; t++) {
        const ull* hc = hD + (t & 1) * HBUF;
        ull*       hn = hD + ((t & 1) ^ 1) * HBUF;

        ull acc[8];
#pragma unroll
        for (int r = 0; r < 8; r++) acc[r] = xv[r];

        // Prefetch next timestep's P rows (hidden under k-loop)
        if (t + 1 < SEQ) {
#pragma unroll
            for (int r = 0; r < 8; r++) {
                const int tok = tok_sh[(slot0 + r) * SEQ + t + 1];
                float2 p = *(const float2*)&g_P[(long)tok * HID + j0];
                xv[r] = add2(pk(p.x, p.y), bh2);
            }
        }

        for (int k0 = 0; k0 < HID; k0 += 16) {
#pragma unroll
            for (int kk = 0; kk < 16; kk++) {
                const int k = k0 + kk;
                const ull w2 = *(const ull*)(Whh_sh + k * HID + j0);
                const ulonglong2* hp = (const ulonglong2*)(hc + k * HSTR + slot0);
                ulonglong2 h01 = hp[0], h23 = hp[1], h45 = hp[2], h67 = hp[3];
                acc[0] = fma2(h01.x, w2, acc[0]);
                acc[1] = fma2(h01.y, w2, acc[1]);
                acc[2] = fma2(h23.x, w2, acc[2]);
                acc[3] = fma2(h23.y, w2, acc[3]);
                acc[4] = fma2(h45.x, w2, acc[4]);
                acc[5] = fma2(h45.y, w2, acc[5]);
                acc[6] = fma2(h67.x, w2, acc[6]);
                acc[7] = fma2(h67.y, w2, acc[7]);
            }
        }

        // tanh + store duplicated h(t+1)
#pragma unroll
        for (int r = 0; r < 8; r++) {
            float2 a = upk(acc[r]);
            vlast[r][0] = tanhf(a.x);
            vlast[r][1] = tanhf(a.y);
        }
#pragma unroll
        for (int i = 0; i < 4; i++) {
            ulonglong2 e0, e1;
            e0.x = pk(vlast[2 * i][0],     vlast[2 * i][0]);
            e0.y = pk(vlast[2 * i + 1][0], vlast[2 * i + 1][0]);
            e1.x = pk(vlast[2 * i][1],     vlast[2 * i][1]);
            e1.y = pk(vlast[2 * i + 1][1], vlast[2 * i + 1][1]);
            *(ulonglong2*)(hn + (j0)     * HSTR + slot0 + 2 * i) = e0;
            *(ulonglong2*)(hn + (j0 + 1) * HSTR + slot0 + 2 * i) = e1;
        }
        __syncthreads();
    }

    // Dense(1) + sigmoid from register-resident final h
    const float2 wd = *(const float2*)&Wd[j0];
    float part[8];
#pragma unroll
    for (int r = 0; r < 8; r++)
        part[r] = vlast[r][0] * wd.x + vlast[r][1] * wd.y;
#pragma unroll
    for (int off = 16; off > 0; off >>= 1)
#pragma unroll
        for (int r = 0; r < 8; r++)
            part[r] += __shfl_xor_sync(0xffffffff, part[r], off);
    if (lane == 0) {
#pragma unroll
        for (int r = 0; r < 8; r++) red[(slot0 + r) * 2 + cg] = part[r];
    }
    __syncthreads();
    if (tid < NSLOT) {
        const float s = red[tid * 2] + red[tid * 2 + 1] + bd[0];
        out[b0 + tid] = 1.f / (1.f + expf(-s));
    }
}

// ---------------------------------------------------------------------------
extern "C" void kernel_launch(void* const* d_in, const int* in_sizes, int n_in,
                              void* d_out, int out_size) {
    const int*   x   = (const int*)d_in[0];
    const float* emb = (const float*)d_in[1];
    const float* Wxh = (const float*)d_in[2];
    const float* Whh = (const float*)d_in[3];
    const float* bh  = (const float*)d_in[4];
    const float* Wd  = (const float*)d_in[5];
    const float* bd  = (const float*)d_in[6];
    float* out = (float*)d_out;

    proj_kernel<<<(VOCAB + 127) / 128, 256>>>(emb, Wxh);

    const int smem = 65536 + 2 * HBUF * 8 + NSLOT * SEQ * 4 + 64 * 4;
    cudaFuncSetAttribute(rnn_kernel, cudaFuncAttributeMaxDynamicSharedMemorySize, smem);
    rnn_kernel<<<RNBLK, 256, smem>>>(x, Whh, bh, Wd, bd, out);
}

// round 4
// speedup vs baseline: 1.7965x; 1.7965x over previous
#include <cuda_runtime.h>
#include <math.h>
#include <stdint.h>

#define VOCAB 50000
#define EMB   300
#define SEQ   80
#define HID   128
#define BATCH 4096

typedef unsigned long long ull;

// Scratch: projected embedding table P = emb @ Wxh (25.6 MB, L2-resident at use)
__device__ float g_P[VOCAB * HID];

// ---- packed f32x2 helpers ----
__device__ __forceinline__ ull fma2(ull a, ull b, ull c) {
    ull d; asm("fma.rn.f32x2 %0, %1, %2, %3;" : "=l"(d) : "l"(a), "l"(b), "l"(c)); return d;
}
__device__ __forceinline__ ull add2(ull a, ull b) {
    ull d; asm("add.rn.f32x2 %0, %1, %2;" : "=l"(d) : "l"(a), "l"(b)); return d;
}
__device__ __forceinline__ ull pk(float lo, float hi) {
    ull d; asm("mov.b64 %0, {%1, %2};" : "=l"(d) : "f"(lo), "f"(hi)); return d;
}
__device__ __forceinline__ float2 upk(ull v) {
    float2 r; asm("mov.b64 {%0, %1}, %2;" : "=f"(r.x), "=f"(r.y) : "l"(v)); return r;
}
__device__ __forceinline__ float ftanh(float x) {
    float xc = fminf(fmaxf(x, -15.f), 15.f);
    float e  = __expf(2.f * xc);
    return __fdividef(e - 1.f, e + 1.f);
}

// ---------------------------------------------------------------------------
// Kernel A: P[v][j] = sum_e emb[v][e] * Wxh[e][j]
// 128x128 tile, TK=20 (300 = 15*20), double-buffered smem, 1 sync/iter.
// 256 threads: tid<128 load A (one emb row, 20 floats), tid>=128 load B.
// 8x8 per-thread scalar-FFMA tile (issue ratio 68/64 -> ~94% fma cap).
// ---------------------------------------------------------------------------
#define PTK 20

__global__ __launch_bounds__(256) void proj_kernel(const float* __restrict__ emb,
                                                   const float* __restrict__ Wxh) {
    __shared__ float As[2][PTK][128];   // [buf][k][row]
    __shared__ float Bs[2][PTK][128];   // [buf][k][col]

    const int tid = threadIdx.x;
    const int v0  = blockIdx.x * 128;
    const int tr  = tid >> 4;   // rows tr*8..+7
    const int tc  = tid & 15;   // cols tc*8..+7

    float acc[8][8];
#pragma unroll
    for (int i = 0; i < 8; i++)
#pragma unroll
        for (int j = 0; j < 8; j++) acc[i][j] = 0.f;

    const bool isA = (tid < 128);
    int av = v0 + tid; if (av > VOCAB - 1) av = VOCAB - 1;   // clamp (junk rows discarded)
    const int t2 = tid - 128;
    const int brow = t2 >> 5;        // 0..3 (per pass of 4 rows)
    const int bcol = (t2 & 31) * 4;

    float4 pf[5];
    // prefetch iter 0
#pragma unroll
    for (int q = 0; q < 5; q++) {
        if (isA) pf[q] = *(const float4*)&emb[(long)av * EMB + 0 + q * 4];
        else     pf[q] = *(const float4*)&Wxh[(0 + q * 4 + brow) * HID + bcol];
    }

    for (int it = 0; it < 15; it++) {
        const int pb = it & 1;
        // commit prefetched tile
        if (isA) {
#pragma unroll
            for (int q = 0; q < 5; q++) {
                As[pb][q * 4 + 0][tid] = pf[q].x;
                As[pb][q * 4 + 1][tid] = pf[q].y;
                As[pb][q * 4 + 2][tid] = pf[q].z;
                As[pb][q * 4 + 3][tid] = pf[q].w;
            }
        } else {
#pragma unroll
            for (int q = 0; q < 5; q++)
                *(float4*)&Bs[pb][q * 4 + brow][bcol] = pf[q];
        }
        __syncthreads();

        // prefetch next iter
        if (it + 1 < 15) {
            const int e0 = (it + 1) * PTK;
#pragma unroll
            for (int q = 0; q < 5; q++) {
                if (isA) pf[q] = *(const float4*)&emb[(long)av * EMB + e0 + q * 4];
                else     pf[q] = *(const float4*)&Wxh[(e0 + q * 4 + brow) * HID + bcol];
            }
        }

        // compute on buffer pb
#pragma unroll
        for (int k = 0; k < PTK; k++) {
            float a[8], b[8];
            *(float4*)&a[0] = *(const float4*)&As[pb][k][tr * 8];
            *(float4*)&a[4] = *(const float4*)&As[pb][k][tr * 8 + 4];
            *(float4*)&b[0] = *(const float4*)&Bs[pb][k][tc * 8];
            *(float4*)&b[4] = *(const float4*)&Bs[pb][k][tc * 8 + 4];
#pragma unroll
            for (int i = 0; i < 8; i++)
#pragma unroll
                for (int j = 0; j < 8; j++) acc[i][j] += a[i] * b[j];
        }
        __syncthreads();
    }

#pragma unroll
    for (int i = 0; i < 8; i++) {
        const int v = v0 + tr * 8 + i;
        if (v < VOCAB) {
            *(float4*)&g_P[(long)v * HID + tc * 8]     = *(float4*)&acc[i][0];
            *(float4*)&g_P[(long)v * HID + tc * 8 + 4] = *(float4*)&acc[i][4];
        }
    }
}

// ---------------------------------------------------------------------------
// Kernel B: recurrence. grid=128, 128 threads (4 warps, 1/SMSP).
// Warp = 8 batch rows x ALL 128 cols; lane = 8 rows x 4 cols (j0=4*lane).
// h buffer is PER-WARP (4 KB, [k][row8] in XOR-swizzled 16B units):
//   logical unit u = 2k+hh  ->  phys u' = u ^ ((u>>3)&7)
// Reads: 2 broadcast LDS.128 per k. Stores: 8 STS.128, 4-way max conflict.
// No __syncthreads in the timestep loop (h is warp-private) - 2 __syncwarp.
// fma2 packed over ROW PAIRS: a-operand (h_r0,h_r1) straight from LDS.128;
// w dups (4 movs/k) ride the ALU pipe. Per k: 16 fma2 + 3 LDS + 4 mov
//   -> FMA2-pipe-bound (32 cyc) with 25% issue slack.
// ---------------------------------------------------------------------------
__global__ __launch_bounds__(128, 1) void rnn_kernel(const int* __restrict__ x,
                                                     const float* __restrict__ Whh,
                                                     const float* __restrict__ bh,
                                                     const float* __restrict__ Wd,
                                                     const float* __restrict__ bd,
                                                     float* __restrict__ out) {
    extern __shared__ char smc[];
    float* Whh_sh = (float*)smc;                      // 65536 B
    float* hball  = (float*)(smc + 65536);            // 4 x 4096 B
    int*   tok_sh = (int*)(smc + 65536 + 16384);      // 10240 B

    const int tid  = threadIdx.x;
    const int lane = tid & 31;
    const int rg   = tid >> 5;
    const int j0   = lane * 4;
    const int b0   = blockIdx.x * 32;

    // ---- init: Whh + tokens into smem ----
    {
        const float4* s = (const float4*)Whh;
        float4* d = (float4*)Whh_sh;
        for (int i = tid; i < HID * HID / 4; i += 128) d[i] = s[i];
        const int4* xs = (const int4*)(x + b0 * SEQ);
        int4* td = (int4*)tok_sh;
        for (int i = tid; i < 32 * SEQ / 4; i += 128) td[i] = xs[i];
    }
    __syncthreads();

    char* hw = (char*)(hball + rg * 1024);
    const int* myTok = tok_sh + (rg * 8) * SEQ;

    // per-thread store offsets: col c (=4*lane+c), half hh -> rows hh*4..+4
    uint32_t st_off[4][2];
#pragma unroll
    for (int c = 0; c < 4; c++)
#pragma unroll
        for (int hh = 0; hh < 2; hh++)
            st_off[c][hh] = (uint32_t)((8 * lane + ((2 * c + hh) ^ (lane & 7))) * 16);

    const float4 bh4 = *(const float4*)(bh + j0);
    ull bhd[4] = {pk(bh4.x, bh4.x), pk(bh4.y, bh4.y), pk(bh4.z, bh4.z), pk(bh4.w, bh4.w)};

    // prefetch t=0 inputs
    float4 xraw[8];
#pragma unroll
    for (int r = 0; r < 8; r++) {
        const int tk = myTok[r * SEQ + 0];
        xraw[r] = *(const float4*)(g_P + tk * HID + j0);
    }

    for (int t = 0; t < SEQ; t++) {
        ull acc[4][4];
#pragma unroll
        for (int p = 0; p < 4; p++) {
            const float* lo = (const float*)&xraw[2 * p];
            const float* hi = (const float*)&xraw[2 * p + 1];
#pragma unroll
            for (int c = 0; c < 4; c++)
                acc[p][c] = add2(pk(lo[c], hi[c]), bhd[c]);
        }

        // prefetch next timestep's P rows (consumed next iteration)
        if (t + 1 < SEQ) {
#pragma unroll
            for (int r = 0; r < 8; r++) {
                const int tk = myTok[r * SEQ + t + 1];
                xraw[r] = *(const float4*)(g_P + tk * HID + j0);
            }
        }

        if (t > 0) {
            const char*  hb = hw;
            const float* wp = Whh_sh + j0;
#pragma unroll 1
            for (int j = 0; j < 4; j++) {
#pragma unroll
                for (int i = 0; i < 32; i++) {
                    const int off = ((2 * i) ^ ((i >> 2) & 7)) * 16;
                    ulonglong2 hA = *(const ulonglong2*)(hb + off);          // rows 0-3
                    ulonglong2 hB = *(const ulonglong2*)(hb + (off ^ 16));   // rows 4-7
                    float4 w = *(const float4*)(wp + i * HID);
                    ull w0 = pk(w.x, w.x), w1 = pk(w.y, w.y);
                    ull w2 = pk(w.z, w.z), w3 = pk(w.w, w.w);
                    acc[0][0] = fma2(hA.x, w0, acc[0][0]);
                    acc[0][1] = fma2(hA.x, w1, acc[0][1]);
                    acc[0][2] = fma2(hA.x, w2, acc[0][2]);
                    acc[0][3] = fma2(hA.x, w3, acc[0][3]);
                    acc[1][0] = fma2(hA.y, w0, acc[1][0]);
                    acc[1][1] = fma2(hA.y, w1, acc[1][1]);
                    acc[1][2] = fma2(hA.y, w2, acc[1][2]);
                    acc[1][3] = fma2(hA.y, w3, acc[1][3]);
                    acc[2][0] = fma2(hB.x, w0, acc[2][0]);
                    acc[2][1] = fma2(hB.x, w1, acc[2][1]);
                    acc[2][2] = fma2(hB.x, w2, acc[2][2]);
                    acc[2][3] = fma2(hB.x, w3, acc[2][3]);
                    acc[3][0] = fma2(hB.y, w0, acc[3][0]);
                    acc[3][1] = fma2(hB.y, w1, acc[3][1]);
                    acc[3][2] = fma2(hB.y, w2, acc[3][2]);
                    acc[3][3] = fma2(hB.y, w3, acc[3][3]);
                }
                hb += 1024;
                wp += 32 * HID;
            }
        }

        __syncwarp();   // all reads of h(t-1) done warp-wide
        // tanh + store h(t) into warp-private buffer
#pragma unroll
        for (int c = 0; c < 4; c++) {
            float2 a0 = upk(acc[0][c]), a1 = upk(acc[1][c]);
            float2 a2 = upk(acc[2][c]), a3 = upk(acc[3][c]);
            float4 v0, v1;
            v0.x = ftanh(a0.x); v0.y = ftanh(a0.y);
            v0.z = ftanh(a1.x); v0.w = ftanh(a1.y);
            v1.x = ftanh(a2.x); v1.y = ftanh(a2.y);
            v1.z = ftanh(a3.x); v1.w = ftanh(a3.y);
            *(float4*)(hw + st_off[c][0]) = v0;
            *(float4*)(hw + st_off[c][1]) = v1;
        }
        __syncwarp();   // stores visible before next step's reads
    }

    // ---- Dense(1) + sigmoid: read back final h from warp buffer ----
    const float4 wd4 = *(const float4*)(Wd + j0);
    const float* wdp = (const float*)&wd4;
    const float  bd0 = bd[0];
    float part[8];
#pragma unroll
    for (int r = 0; r < 8; r++) part[r] = 0.f;
#pragma unroll
    for (int c = 0; c < 4; c++) {
        float4 v0 = *(const float4*)(hw + st_off[c][0]);
        float4 v1 = *(const float4*)(hw + st_off[c][1]);
        const float wc = wdp[c];
        part[0] += v0.x * wc; part[1] += v0.y * wc;
        part[2] += v0.z * wc; part[3] += v0.w * wc;
        part[4] += v1.x * wc; part[5] += v1.y * wc;
        part[6] += v1.z * wc; part[7] += v1.w * wc;
    }
#pragma unroll
    for (int off = 16; off > 0; off >>= 1)
#pragma unroll
        for (int r = 0; r < 8; r++)
            part[r] += __shfl_xor_sync(0xffffffff, part[r], off);
    if (lane == 0) {
#pragma unroll
        for (int r = 0; r < 8; r++)
            out[b0 + rg * 8 + r] = __fdividef(1.f, 1.f + __expf(-(part[r] + bd0)));
    }
}

// ---------------------------------------------------------------------------
extern "C" void kernel_launch(void* const* d_in, const int* in_sizes, int n_in,
                              void* d_out, int out_size) {
    const int*   x   = (const int*)d_in[0];
    const float* emb = (const float*)d_in[1];
    const float* Wxh = (const float*)d_in[2];
    const float* Whh = (const float*)d_in[3];
    const float* bh  = (const float*)d_in[4];
    const float* Wd  = (const float*)d_in[5];
    const float* bd  = (const float*)d_in[6];
    float* out = (float*)d_out;

    proj_kernel<<<(VOCAB + 127) / 128, 256>>>(emb, Wxh);

    const int smem = 65536 + 16384 + 32 * SEQ * 4;   // 92160 B
    cudaFuncSetAttribute(rnn_kernel, cudaFuncAttributeMaxDynamicSharedMemorySize, smem);
    rnn_kernel<<<BATCH / 32, 128, smem>>>(x, Whh, bh, Wd, bd, out);
}